// round 16
// baseline (speedup 1.0000x reference)
#include <cuda_runtime.h>

#define HIDSZ 256
#define NAGENTS 8
#define NMODELS 64
#define NACTIONS 16
#define BN 256
#define IN_DIM 512
#define COMM_OUT (HIDSZ * NAGENTS)   // 2048

#define OFF_ACT  0
#define OFF_BASE (BN * NACTIONS)          // 4096
#define OFF_HID  (OFF_BASE + BN)          // 4352
#define OFF_COMM (OFF_HID + BN * HIDSZ)   // 69888

// ---------------- device scratch (no allocation) ----------------------------
__device__ int g_rows[BN];      // row indices, sorted by model
__device__ int g_nchunks;
__device__ int g_cm[BN], g_cs[BN], g_cn[BN];   // chunk: model, start, count

__device__ __forceinline__ void red_add_v4(float* dst, float4 v) {
    asm volatile("red.global.add.v4.f32 [%0], {%1, %2, %3, %4};"
                 :: "l"(dst), "f"(v.x), "f"(v.y), "f"(v.z), "f"(v.w)
                 : "memory");
}

__device__ __forceinline__ void l2_prefetch(const void* p) {
    asm volatile("prefetch.global.L2 [%0];" :: "l"(p));
}

// ---------------------------------------------------------------------------
// Grouping body (one block of launch 1; launch 2 consumes the lists).
// ---------------------------------------------------------------------------
__device__ void group_body(const int* __restrict__ ids) {
    __shared__ int cnt[NMODELS];
    __shared__ int off[NMODELS];
    __shared__ int coff[NMODELS];
    __shared__ int cur[NMODELS];
    __shared__ int tmp[NMODELS];
    const int t = threadIdx.x;

    if (t < NMODELS) cnt[t] = 0;
    __syncthreads();
    int m = -1;
    if (t < BN) { m = ids[t]; atomicAdd(&cnt[m], 1); }
    __syncthreads();

    if (t < NMODELS) {
        off[t] = cnt[t];
        coff[t] = (cnt[t] + 7) >> 3;
    }
    __syncthreads();
    #pragma unroll
    for (int d = 1; d < NMODELS; d <<= 1) {
        int a = 0, b = 0;
        if (t < NMODELS && t >= d) { a = off[t - d]; b = coff[t - d]; }
        __syncthreads();
        if (t < NMODELS && t >= d) { off[t] += a; coff[t] += b; }
        __syncthreads();
    }
    if (t < NMODELS) {
        tmp[t] = off[t] - cnt[t];
        cur[t] = tmp[t];
        if (t == NMODELS - 1) g_nchunks = coff[t];
    }
    __syncthreads();
    if (t < NMODELS) {
        int co = coff[t] - ((cnt[t] + 7) >> 3);
        int s = tmp[t], n = cnt[t];
        for (int c = 0; c < n; c += 8) {
            g_cm[co] = t;
            g_cs[co] = s + c;
            g_cn[co] = min(8, n - c);
            co++;
        }
    }
    __syncthreads();
    if (t < BN) {
        int pos = atomicAdd(&cur[m], 1);
        g_rows[pos] = t;
    }
}

// ---------------------------------------------------------------------------
// Launch 1: hid = relu(inp@enc_w + enc_b + prev@rnn_w[m] + rnn_b[m] + comm_sum)
// Grid (81, 8): x<64 = 4-row tile, y = 32-col tile (8 quads).
//               x==64,y==0 = grouping.  x in [65,68] = zero comm region.
//               x in [69,80] = L2-prefetch 48 MB prefix of comm_w.
// ---------------------------------------------------------------------------
__global__ void __launch_bounds__(256)
hid_group_kernel(const float* __restrict__ inp,
                 const float* __restrict__ prev,
                 const float* __restrict__ comm_in,
                 const int*   __restrict__ ids,
                 const float* __restrict__ enc_w,
                 const float* __restrict__ enc_b,
                 const float* __restrict__ rnn_w,
                 const float* __restrict__ rnn_b,
                 const float* __restrict__ comm_w,
                 float* __restrict__ out) {
    const int t = threadIdx.x;
    if (blockIdx.x >= 69) {
        // L2-prefetch comm_w prefix: 96 blocks x 512 KB = 48 MB
        const int idx = (blockIdx.x - 69) * 8 + blockIdx.y;   // 0..95
        const char* base = (const char*)comm_w + (size_t)idx * 524288;
        #pragma unroll
        for (int i = 0; i < 16; i++)
            l2_prefetch(base + ((size_t)i * 256 + t) * 128);
        return;
    }
    if (blockIdx.x >= 65) {
        // zero-fill comm output region: 32 blocks x 4096 float4 = 2 MB
        const int idx = (blockIdx.x - 65) * 8 + blockIdx.y;   // 0..31
        float4* dst = (float4*)(out + OFF_COMM) + (size_t)idx * 4096;
        const float4 z = make_float4(0.f, 0.f, 0.f, 0.f);
        #pragma unroll
        for (int i = 0; i < 16; i++) dst[t + 256 * i] = z;
        return;
    }
    if (blockIdx.x == 64) { if (blockIdx.y == 0) group_body(ids); return; }

    __shared__ __align__(16) char smem_raw[16 * 1024];
    float (*sx)[IN_DIM] = (float (*)[IN_DIM])smem_raw;              // 8 KB
    float (*sp)[HIDSZ]  = (float (*)[HIDSZ])(smem_raw + 8192);      // 4 KB
    float4 (*part)[4][8] = (float4 (*)[4][8])smem_raw;              // 16 KB (aliases)
    __shared__ int sm[4];

    const int r0  = blockIdx.x * 4;
    const int cq0 = blockIdx.y * 8;      // quad base (8 quads = 32 cols)

    // load 4 rows of inp (512 float4) and prev (256 float4)
    const float4* inp4 = (const float4*)(inp + (size_t)r0 * IN_DIM);
    #pragma unroll
    for (int i = 0; i < 2; i++) ((float4*)sx)[t + 256 * i] = inp4[t + 256 * i];
    const float4* prev4 = (const float4*)(prev + (size_t)r0 * HIDSZ);
    ((float4*)sp)[t] = prev4[t];
    if (t < 4) sm[t] = ids[r0 + t];
    __syncthreads();

    const int q = t & 7, s = t >> 3;     // 8 quads x 32 slices
    float4 acc[4];
    #pragma unroll
    for (int r = 0; r < 4; r++) acc[r] = make_float4(0.f, 0.f, 0.f, 0.f);

    // enc: k in [s*16, s*16+16)
    {
        const float4* w4 = (const float4*)enc_w + cq0 + q;
        #pragma unroll 4
        for (int k = s * 16; k < s * 16 + 16; k++) {
            float4 wv = w4[(size_t)k * 64];
            #pragma unroll
            for (int r = 0; r < 4; r++) {
                float x = sx[r][k];
                acc[r].x += x * wv.x; acc[r].y += x * wv.y;
                acc[r].z += x * wv.z; acc[r].w += x * wv.w;
            }
        }
    }
    // rnn: k in [s*8, s*8+8), 4 independent model weight streams
    {
        const float4* wr[4];
        #pragma unroll
        for (int r = 0; r < 4; r++)
            wr[r] = (const float4*)(rnn_w + (size_t)sm[r] * HIDSZ * HIDSZ) + cq0 + q;
        #pragma unroll 2
        for (int k = s * 8; k < s * 8 + 8; k++) {
            #pragma unroll
            for (int r = 0; r < 4; r++) {
                float4 wv = wr[r][(size_t)k * 64];
                float x = sp[r][k];
                acc[r].x += x * wv.x; acc[r].y += x * wv.y;
                acc[r].z += x * wv.z; acc[r].w += x * wv.w;
            }
        }
    }
    __syncthreads();   // done reading sx/sp; part aliases them
    #pragma unroll
    for (int r = 0; r < 4; r++) part[s][r][q] = acc[r];
    __syncthreads();

    // reduce 32 slices -> (row, quad); finalize
    if (t < 32) {
        const int r = t >> 3, qq = t & 7;
        float4 v = part[0][r][qq];
        #pragma unroll
        for (int s2 = 1; s2 < 32; s2++) {
            float4 p = part[s2][r][qq];
            v.x += p.x; v.y += p.y; v.z += p.z; v.w += p.w;
        }
        float4 eb = ((const float4*)enc_b)[cq0 + qq];
        float4 rb = ((const float4*)(rnn_b + (size_t)sm[r] * HIDSZ))[cq0 + qq];
        v.x += eb.x + rb.x; v.y += eb.y + rb.y;
        v.z += eb.z + rb.z; v.w += eb.w + rb.w;
        const float4* cb = (const float4*)comm_in + (size_t)(r0 + r) * (NAGENTS * HIDSZ / 4) + cq0 + qq;
        #pragma unroll
        for (int a = 0; a < NAGENTS; a++) {
            float4 cv = cb[a * 64];
            v.x += cv.x; v.y += cv.y; v.z += cv.z; v.w += cv.w;
        }
        v.x = fmaxf(v.x, 0.f); v.y = fmaxf(v.y, 0.f);
        v.z = fmaxf(v.z, 0.f); v.w = fmaxf(v.w, 0.f);
        ((float4*)(out + OFF_HID + (size_t)(r0 + r) * HIDSZ))[cq0 + qq] = v;
    }
}

// ---------------------------------------------------------------------------
// act/baseline/softmax body: one 256-thread block per row.
// ---------------------------------------------------------------------------
__device__ void act_body(int b,
                         const int*   __restrict__ ids,
                         const float* __restrict__ act_w,
                         const float* __restrict__ act_b,
                         const float* __restrict__ base_w,
                         const float* __restrict__ base_b,
                         float* __restrict__ out) {
    const int t = threadIdx.x;
    __shared__ float sh[HIDSZ];
    __shared__ float apart[NACTIONS][16];
    __shared__ float bres[8];

    if (t < 64) ((float4*)sh)[t] = ((const float4*)(out + OFF_HID + (size_t)b * HIDSZ))[t];
    const int m = ids[b];
    __syncthreads();

    {
        const int o = t & 15, sl = t >> 4;
        const float* aw = act_w + (size_t)m * HIDSZ * NACTIONS + o;
        float p = 0.f;
        #pragma unroll
        for (int kk = 0; kk < 16; kk++) {
            int k = sl * 16 + kk;
            p += sh[k] * aw[(size_t)k * NACTIONS];
        }
        apart[o][sl] = p;
    }
    {
        float bp = sh[t] * base_w[(size_t)m * HIDSZ + t];
        #pragma unroll
        for (int o = 16; o > 0; o >>= 1) bp += __shfl_xor_sync(0xffffffffu, bp, o);
        if ((t & 31) == 0) bres[t >> 5] = bp;
    }
    __syncthreads();

    if (t < NACTIONS) {
        float l = act_b[m * NACTIONS + t];
        #pragma unroll
        for (int sl = 0; sl < 16; sl++) l += apart[t][sl];
        float mx = l;
        #pragma unroll
        for (int o = 8; o > 0; o >>= 1) mx = fmaxf(mx, __shfl_xor_sync(0x0000ffffu, mx, o, 16));
        float e = expf(l - mx);
        float ssum = e;
        #pragma unroll
        for (int o = 8; o > 0; o >>= 1) ssum += __shfl_xor_sync(0x0000ffffu, ssum, o, 16);
        out[OFF_ACT + (size_t)b * NACTIONS + t] = e / ssum;
    } else if (t == 16) {
        float v = base_b[m];
        #pragma unroll
        for (int w8 = 0; w8 < 8; w8++) v += bres[w8];
        out[OFF_BASE + b] = v;
    }
}

// ---------------------------------------------------------------------------
// Launch 2: comm GEMM, k-split x4 with vector-atomic accumulation (+ act).
// Grid (128, 8): x<96 comm chunk slot; y = kquarter*2 + colhalf.
//                x>=96: act row = (x-96)*8 + y.
// ---------------------------------------------------------------------------
template <int R>
__device__ __forceinline__ void comm_mm(const float4* __restrict__ w4,
                                        const float4 (*__restrict__ sh4)[16],
                                        float4 binit, float4* acc) {
    #pragma unroll
    for (int r = 0; r < R; r++) acc[r] = binit;
    #pragma unroll 2
    for (int kq = 0; kq < 16; kq++) {
        float4 w0 = w4[(size_t)(4 * kq + 0) * (COMM_OUT / 4)];
        float4 w1 = w4[(size_t)(4 * kq + 1) * (COMM_OUT / 4)];
        float4 w2 = w4[(size_t)(4 * kq + 2) * (COMM_OUT / 4)];
        float4 w3 = w4[(size_t)(4 * kq + 3) * (COMM_OUT / 4)];
        #pragma unroll
        for (int r = 0; r < R; r++) {
            float4 h = sh4[r][kq];
            acc[r].x += h.x * w0.x + h.y * w1.x + h.z * w2.x + h.w * w3.x;
            acc[r].y += h.x * w0.y + h.y * w1.y + h.z * w2.y + h.w * w3.y;
            acc[r].z += h.x * w0.z + h.y * w1.z + h.z * w2.z + h.w * w3.z;
            acc[r].w += h.x * w0.w + h.y * w1.w + h.z * w2.w + h.w * w3.w;
        }
    }
}

__global__ void __launch_bounds__(256, 4)
comm_act_kernel(const float* __restrict__ comm_w,
                const float* __restrict__ comm_b,
                const int*   __restrict__ ids,
                const float* __restrict__ act_w,
                const float* __restrict__ act_b,
                const float* __restrict__ base_w,
                const float* __restrict__ base_b,
                float* __restrict__ out) {
    if (blockIdx.x >= 96) {
        act_body((blockIdx.x - 96) * 8 + blockIdx.y,
                 ids, act_w, act_b, base_w, base_b, out);
        return;
    }
    const int ci = blockIdx.x;
    if (ci >= g_nchunks) return;
    const int m  = g_cm[ci];
    const int s0 = g_cs[ci];
    const int n  = g_cn[ci];
    const int t  = threadIdx.x;
    const int kq4     = blockIdx.y >> 1;           // k-quarter: [kq4*64, kq4*64+64)
    const int colhalf = blockIdx.y & 1;
    const int colq = colhalf * 256 + t;            // quad index (4 cols)

    __shared__ float4 sh4[8][16];                  // 8 rows x 64 floats (k-quarter)
    __shared__ int    rows[8];
    if (t < 8) rows[t] = (t < n) ? g_rows[s0 + t] : 0;
    __syncthreads();

    const float4* hid4 = (const float4*)(out + OFF_HID);
    if (t < 128) {
        const int r = t >> 4, q = t & 15;          // 8 x 16 = 128 quads
        sh4[r][q] = (r < n)
            ? hid4[(size_t)rows[r] * 64 + kq4 * 16 + q]
            : make_float4(0.f, 0.f, 0.f, 0.f);
    }
    __syncthreads();

    float4 binit = make_float4(0.f, 0.f, 0.f, 0.f);
    if (kq4 == 0) binit = ((const float4*)(comm_b + (size_t)m * COMM_OUT))[colq];

    const float4* w4 = (const float4*)(comm_w + (size_t)m * HIDSZ * COMM_OUT)
                       + (size_t)kq4 * 64 * (COMM_OUT / 4) + colq;

    float4 acc[8];
    switch (n) {
        case 8: comm_mm<8>(w4, sh4, binit, acc); break;
        case 7: comm_mm<7>(w4, sh4, binit, acc); break;
        case 6: comm_mm<6>(w4, sh4, binit, acc); break;
        case 5: comm_mm<5>(w4, sh4, binit, acc); break;
        case 4: comm_mm<4>(w4, sh4, binit, acc); break;
        case 3: comm_mm<3>(w4, sh4, binit, acc); break;
        case 2: comm_mm<2>(w4, sh4, binit, acc); break;
        default: comm_mm<1>(w4, sh4, binit, acc); break;
    }

    for (int r = 0; r < n; r++) {
        float* dst = out + OFF_COMM + (size_t)rows[r] * COMM_OUT + colq * 4;
        red_add_v4(dst, acc[r]);
    }
}

// ---------------------------------------------------------------------------
extern "C" void kernel_launch(void* const* d_in, const int* in_sizes, int n_in,
                              void* d_out, int out_size) {
    const float* inp      = (const float*)d_in[0];   // [256, 512]
    const float* prev_hid = (const float*)d_in[1];   // [256, 256]
    const float* comm_in  = (const float*)d_in[2];   // [256, 8, 256]
    const int*   ids      = (const int*)  d_in[3];   // [256]
    const float* enc_w    = (const float*)d_in[4];   // [512, 256]
    const float* enc_b    = (const float*)d_in[5];   // [256]
    const float* rnn_w    = (const float*)d_in[6];   // [64, 256, 256]
    const float* rnn_b    = (const float*)d_in[7];   // [64, 256]
    const float* act_w    = (const float*)d_in[8];   // [64, 256, 16]
    const float* act_b    = (const float*)d_in[9];   // [64, 16]
    const float* base_w   = (const float*)d_in[10];  // [64, 256, 1]
    const float* base_b   = (const float*)d_in[11];  // [64, 1]
    const float* comm_w   = (const float*)d_in[12];  // [64, 256, 2048]
    const float* comm_b   = (const float*)d_in[13];  // [64, 2048]
    float* out = (float*)d_out;

    hid_group_kernel<<<dim3(81, 8), 256>>>(inp, prev_hid, comm_in, ids,
                                           enc_w, enc_b, rnn_w, rnn_b,
                                           comm_w, out);
    comm_act_kernel<<<dim3(128, 8), 256>>>(comm_w, comm_b, ids,
                                           act_w, act_b, base_w, base_b, out);
}

// round 17
// speedup vs baseline: 1.0042x; 1.0042x over previous
#include <cuda_runtime.h>

#define HIDSZ 256
#define NAGENTS 8
#define NMODELS 64
#define NACTIONS 16
#define BN 256
#define IN_DIM 512
#define COMM_OUT (HIDSZ * NAGENTS)   // 2048

#define OFF_ACT  0
#define OFF_BASE (BN * NACTIONS)          // 4096
#define OFF_HID  (OFF_BASE + BN)          // 4352
#define OFF_COMM (OFF_HID + BN * HIDSZ)   // 69888

// Fused grid layout (1D). Producers first (fill wave 1), consumers after.
//   [0, 512)      hid: row-block = bid>>3 (4 rows), col-tile = bid&7 (32 cols)
//   512           grouping
//   [513, 545)    zero-fill comm output region (32 blocks)
//   [545, 1313)   comm: 96 chunk slots x 8 (k-quarter x col-half)
//   [1313, 1569)  act: row = bid - 1313
#define BID_GROUP 512
#define BID_ZERO  513
#define BID_COMM  545
#define BID_ACT   1313
#define NBLOCKS   1569
#define NCONSUMERS 1024   // 768 comm + 256 act

// ---------------- device scratch + flags (no allocation) --------------------
__device__ int g_rows[BN];
__device__ int g_nchunks;
__device__ int g_cm[BN], g_cs[BN], g_cn[BN];
__device__ int g_rowflag[BN];    // -> 8 when row's hid complete
__device__ int g_group_done;
__device__ int g_zf_done;        // -> 32 when comm region zeroed
__device__ int g_done_ct;        // consumer count; last resets flags

__device__ __forceinline__ void red_add_v4(float* dst, float4 v) {
    asm volatile("red.global.add.v4.f32 [%0], {%1, %2, %3, %4};"
                 :: "l"(dst), "f"(v.x), "f"(v.y), "f"(v.z), "f"(v.w)
                 : "memory");
}

__device__ __forceinline__ void spin_ge(int* p, int target) {
    while (atomicAdd(p, 0) < target) __nanosleep(32);
}

// ---------------------------------------------------------------------------
__device__ void group_body(const int* __restrict__ ids) {
    __shared__ int cnt[NMODELS];
    __shared__ int off[NMODELS];
    __shared__ int coff[NMODELS];
    __shared__ int cur[NMODELS];
    __shared__ int tmp[NMODELS];
    const int t = threadIdx.x;

    if (t < NMODELS) cnt[t] = 0;
    __syncthreads();
    int m = -1;
    if (t < BN) { m = ids[t]; atomicAdd(&cnt[m], 1); }
    __syncthreads();

    if (t < NMODELS) {
        off[t] = cnt[t];
        coff[t] = (cnt[t] + 7) >> 3;
    }
    __syncthreads();
    #pragma unroll
    for (int d = 1; d < NMODELS; d <<= 1) {
        int a = 0, b = 0;
        if (t < NMODELS && t >= d) { a = off[t - d]; b = coff[t - d]; }
        __syncthreads();
        if (t < NMODELS && t >= d) { off[t] += a; coff[t] += b; }
        __syncthreads();
    }
    if (t < NMODELS) {
        tmp[t] = off[t] - cnt[t];
        cur[t] = tmp[t];
        if (t == NMODELS - 1) g_nchunks = coff[t];
    }
    __syncthreads();
    if (t < NMODELS) {
        int co = coff[t] - ((cnt[t] + 7) >> 3);
        int s = tmp[t], n = cnt[t];
        for (int c = 0; c < n; c += 8) {
            g_cm[co] = t;
            g_cs[co] = s + c;
            g_cn[co] = min(8, n - c);
            co++;
        }
    }
    __syncthreads();
    if (t < BN) {
        int pos = atomicAdd(&cur[m], 1);
        g_rows[pos] = t;
    }
    __syncthreads();
    if (t == 0) { __threadfence(); atomicExch(&g_group_done, 1); }
}

// ---------------------------------------------------------------------------
// hid tile: 4 rows x 32 cols.  q = t&7 (8 quads), s = t>>3 (32 k-slices).
// ---------------------------------------------------------------------------
__device__ void hid_body(int bx, int by,
                         const float* __restrict__ inp,
                         const float* __restrict__ prev,
                         const float* __restrict__ comm_in,
                         const int*   __restrict__ ids,
                         const float* __restrict__ enc_w,
                         const float* __restrict__ enc_b,
                         const float* __restrict__ rnn_w,
                         const float* __restrict__ rnn_b,
                         float* __restrict__ out,
                         char* smem_raw) {
    float (*sx)[IN_DIM] = (float (*)[IN_DIM])smem_raw;              // 8 KB
    float (*sp)[HIDSZ]  = (float (*)[HIDSZ])(smem_raw + 8192);      // 4 KB
    float4 (*part)[4][8] = (float4 (*)[4][8])smem_raw;              // 16 KB (aliases)
    __shared__ int sm[4];

    const int t   = threadIdx.x;
    const int r0  = bx * 4;
    const int cq0 = by * 8;

    const float4* inp4 = (const float4*)(inp + (size_t)r0 * IN_DIM);
    #pragma unroll
    for (int i = 0; i < 2; i++) ((float4*)sx)[t + 256 * i] = inp4[t + 256 * i];
    const float4* prev4 = (const float4*)(prev + (size_t)r0 * HIDSZ);
    ((float4*)sp)[t] = prev4[t];
    if (t < 4) sm[t] = ids[r0 + t];
    __syncthreads();

    const int q = t & 7, s = t >> 3;
    float4 acc[4];
    #pragma unroll
    for (int r = 0; r < 4; r++) acc[r] = make_float4(0.f, 0.f, 0.f, 0.f);

    // enc: k in [s*16, s*16+16)
    {
        const float4* w4 = (const float4*)enc_w + cq0 + q;
        #pragma unroll 4
        for (int k = s * 16; k < s * 16 + 16; k++) {
            float4 wv = w4[(size_t)k * 64];
            #pragma unroll
            for (int r = 0; r < 4; r++) {
                float x = sx[r][k];
                acc[r].x += x * wv.x; acc[r].y += x * wv.y;
                acc[r].z += x * wv.z; acc[r].w += x * wv.w;
            }
        }
    }
    // rnn: k in [s*8, s*8+8)
    {
        const float4* wr[4];
        #pragma unroll
        for (int r = 0; r < 4; r++)
            wr[r] = (const float4*)(rnn_w + (size_t)sm[r] * HIDSZ * HIDSZ) + cq0 + q;
        #pragma unroll 2
        for (int k = s * 8; k < s * 8 + 8; k++) {
            #pragma unroll
            for (int r = 0; r < 4; r++) {
                float4 wv = wr[r][(size_t)k * 64];
                float x = sp[r][k];
                acc[r].x += x * wv.x; acc[r].y += x * wv.y;
                acc[r].z += x * wv.z; acc[r].w += x * wv.w;
            }
        }
    }
    __syncthreads();
    #pragma unroll
    for (int r = 0; r < 4; r++) part[s][r][q] = acc[r];
    __syncthreads();

    if (t < 32) {
        const int r = t >> 3, qq = t & 7;
        float4 v = part[0][r][qq];
        #pragma unroll
        for (int s2 = 1; s2 < 32; s2++) {
            float4 p = part[s2][r][qq];
            v.x += p.x; v.y += p.y; v.z += p.z; v.w += p.w;
        }
        float4 eb = ((const float4*)enc_b)[cq0 + qq];
        float4 rb = ((const float4*)(rnn_b + (size_t)sm[r] * HIDSZ))[cq0 + qq];
        v.x += eb.x + rb.x; v.y += eb.y + rb.y;
        v.z += eb.z + rb.z; v.w += eb.w + rb.w;
        const float4* cb = (const float4*)comm_in + (size_t)(r0 + r) * (NAGENTS * HIDSZ / 4) + cq0 + qq;
        #pragma unroll
        for (int a = 0; a < NAGENTS; a++) {
            float4 cv = cb[a * 64];
            v.x += cv.x; v.y += cv.y; v.z += cv.z; v.w += cv.w;
        }
        v.x = fmaxf(v.x, 0.f); v.y = fmaxf(v.y, 0.f);
        v.z = fmaxf(v.z, 0.f); v.w = fmaxf(v.w, 0.f);
        ((float4*)(out + OFF_HID + (size_t)(r0 + r) * HIDSZ))[cq0 + qq] = v;
    }
    __syncthreads();
    if (t < 4) { __threadfence(); atomicAdd(&g_rowflag[r0 + t], 1); }
}

// ---------------------------------------------------------------------------
__device__ void consumer_done() {
    __syncthreads();
    if (threadIdx.x == 0) {
        int v = atomicAdd(&g_done_ct, 1);
        if (v == NCONSUMERS - 1) {
            for (int i = 0; i < BN; i++) g_rowflag[i] = 0;
            g_zf_done = 0;
            g_group_done = 0;
            __threadfence();
            g_done_ct = 0;
        }
    }
}

// ---------------------------------------------------------------------------
__device__ void act_body(int b,
                         const int*   __restrict__ ids,
                         const float* __restrict__ act_w,
                         const float* __restrict__ act_b,
                         const float* __restrict__ base_w,
                         const float* __restrict__ base_b,
                         float* __restrict__ out) {
    const int t = threadIdx.x;
    __shared__ float sh[HIDSZ];
    __shared__ float apart[NACTIONS][16];
    __shared__ float bres[8];

    if (t == 0) spin_ge(&g_rowflag[b], 8);
    __syncthreads();
    __threadfence();

    if (t < 64) ((float4*)sh)[t] = ((const float4*)(out + OFF_HID + (size_t)b * HIDSZ))[t];
    const int m = ids[b];
    __syncthreads();

    {
        const int o = t & 15, sl = t >> 4;
        const float* aw = act_w + (size_t)m * HIDSZ * NACTIONS + o;
        float p = 0.f;
        #pragma unroll
        for (int kk = 0; kk < 16; kk++) {
            int k = sl * 16 + kk;
            p += sh[k] * aw[(size_t)k * NACTIONS];
        }
        apart[o][sl] = p;
    }
    {
        float bp = sh[t] * base_w[(size_t)m * HIDSZ + t];
        #pragma unroll
        for (int o = 16; o > 0; o >>= 1) bp += __shfl_xor_sync(0xffffffffu, bp, o);
        if ((t & 31) == 0) bres[t >> 5] = bp;
    }
    __syncthreads();

    if (t < NACTIONS) {
        float l = act_b[m * NACTIONS + t];
        #pragma unroll
        for (int sl = 0; sl < 16; sl++) l += apart[t][sl];
        float mx = l;
        #pragma unroll
        for (int o = 8; o > 0; o >>= 1) mx = fmaxf(mx, __shfl_xor_sync(0x0000ffffu, mx, o, 16));
        float e = expf(l - mx);
        float ssum = e;
        #pragma unroll
        for (int o = 8; o > 0; o >>= 1) ssum += __shfl_xor_sync(0x0000ffffu, ssum, o, 16);
        out[OFF_ACT + (size_t)b * NACTIONS + t] = e / ssum;
    } else if (t == 16) {
        float v = base_b[m];
        #pragma unroll
        for (int w8 = 0; w8 < 8; w8++) v += bres[w8];
        out[OFF_BASE + b] = v;
    }
}

// ---------------------------------------------------------------------------
template <int R>
__device__ __forceinline__ void comm_mm(const float4* __restrict__ w4,
                                        const float4 (*__restrict__ sh4)[16],
                                        float4 binit, float4* acc) {
    #pragma unroll
    for (int r = 0; r < R; r++) acc[r] = binit;
    #pragma unroll 2
    for (int kq = 0; kq < 16; kq++) {
        float4 w0 = w4[(size_t)(4 * kq + 0) * (COMM_OUT / 4)];
        float4 w1 = w4[(size_t)(4 * kq + 1) * (COMM_OUT / 4)];
        float4 w2 = w4[(size_t)(4 * kq + 2) * (COMM_OUT / 4)];
        float4 w3 = w4[(size_t)(4 * kq + 3) * (COMM_OUT / 4)];
        #pragma unroll
        for (int r = 0; r < R; r++) {
            float4 h = sh4[r][kq];
            acc[r].x += h.x * w0.x + h.y * w1.x + h.z * w2.x + h.w * w3.x;
            acc[r].y += h.x * w0.y + h.y * w1.y + h.z * w2.y + h.w * w3.y;
            acc[r].z += h.x * w0.z + h.y * w1.z + h.z * w2.z + h.w * w3.z;
            acc[r].w += h.x * w0.w + h.y * w1.w + h.z * w2.w + h.w * w3.w;
        }
    }
}

__device__ void comm_body(int slot,
                          const float* __restrict__ comm_w,
                          const float* __restrict__ comm_b,
                          float* __restrict__ out) {
    const int ci      = slot >> 3;
    const int kq4     = (slot & 7) >> 1;
    const int colhalf = slot & 1;
    const int t = threadIdx.x;

    if (t == 0) spin_ge(&g_group_done, 1);
    __syncthreads();
    __threadfence();

    if (ci >= g_nchunks) { consumer_done(); return; }
    const int m  = g_cm[ci];
    const int s0 = g_cs[ci];
    const int n  = g_cn[ci];
    const int colq = colhalf * 256 + t;

    __shared__ float4 sh4[8][16];
    __shared__ int    rows[8];
    if (t < 8) rows[t] = (t < n) ? g_rows[s0 + t] : 0;
    __syncthreads();
    if (t < n) spin_ge(&g_rowflag[rows[t]], 8);
    __syncthreads();
    __threadfence();

    const float4* hid4 = (const float4*)(out + OFF_HID);
    if (t < 128) {
        const int r = t >> 4, q = t & 15;
        sh4[r][q] = (r < n)
            ? hid4[(size_t)rows[r] * 64 + kq4 * 16 + q]
            : make_float4(0.f, 0.f, 0.f, 0.f);
    }
    __syncthreads();

    float4 binit = make_float4(0.f, 0.f, 0.f, 0.f);
    if (kq4 == 0) binit = ((const float4*)(comm_b + (size_t)m * COMM_OUT))[colq];

    const float4* w4 = (const float4*)(comm_w + (size_t)m * HIDSZ * COMM_OUT)
                       + (size_t)kq4 * 64 * (COMM_OUT / 4) + colq;

    float4 acc[8];
    switch (n) {
        case 8: comm_mm<8>(w4, sh4, binit, acc); break;
        case 7: comm_mm<7>(w4, sh4, binit, acc); break;
        case 6: comm_mm<6>(w4, sh4, binit, acc); break;
        case 5: comm_mm<5>(w4, sh4, binit, acc); break;
        case 4: comm_mm<4>(w4, sh4, binit, acc); break;
        case 3: comm_mm<3>(w4, sh4, binit, acc); break;
        case 2: comm_mm<2>(w4, sh4, binit, acc); break;
        default: comm_mm<1>(w4, sh4, binit, acc); break;
    }

    if (t == 0) spin_ge(&g_zf_done, 32);
    __syncthreads();

    for (int r = 0; r < n; r++) {
        float* dst = out + OFF_COMM + (size_t)rows[r] * COMM_OUT + colq * 4;
        red_add_v4(dst, acc[r]);
    }
    consumer_done();
}

// ---------------------------------------------------------------------------
__global__ void __launch_bounds__(256, 4)
fused_kernel(const float* __restrict__ inp,
             const float* __restrict__ prev,
             const float* __restrict__ comm_in,
             const int*   __restrict__ ids,
             const float* __restrict__ enc_w,
             const float* __restrict__ enc_b,
             const float* __restrict__ rnn_w,
             const float* __restrict__ rnn_b,
             const float* __restrict__ act_w,
             const float* __restrict__ act_b,
             const float* __restrict__ base_w,
             const float* __restrict__ base_b,
             const float* __restrict__ comm_w,
             const float* __restrict__ comm_b,
             float* __restrict__ out) {
    __shared__ __align__(16) char smem_raw[16 * 1024];
    const int bid = blockIdx.x;
    const int t = threadIdx.x;

    if (bid < BID_GROUP) {
        hid_body(bid >> 3, bid & 7, inp, prev, comm_in, ids,
                 enc_w, enc_b, rnn_w, rnn_b, out, smem_raw);
    } else if (bid == BID_GROUP) {
        group_body(ids);
    } else if (bid < BID_COMM) {
        // zero-fill comm region: 32 blocks x 4096 float4 = 2 MB
        const int idx = bid - BID_ZERO;
        float4* dst = (float4*)(out + OFF_COMM) + (size_t)idx * 4096;
        const float4 z = make_float4(0.f, 0.f, 0.f, 0.f);
        #pragma unroll
        for (int i = 0; i < 16; i++) dst[t + 256 * i] = z;
        __syncthreads();
        if (t == 0) { __threadfence(); atomicAdd(&g_zf_done, 1); }
    } else if (bid < BID_ACT) {
        comm_body(bid - BID_COMM, comm_w, comm_b, out);
    } else {
        act_body(bid - BID_ACT, ids, act_w, act_b, base_w, base_b, out);
        consumer_done();
    }
}

// ---------------------------------------------------------------------------
extern "C" void kernel_launch(void* const* d_in, const int* in_sizes, int n_in,
                              void* d_out, int out_size) {
    const float* inp      = (const float*)d_in[0];
    const float* prev_hid = (const float*)d_in[1];
    const float* comm_in  = (const float*)d_in[2];
    const int*   ids      = (const int*)  d_in[3];
    const float* enc_w    = (const float*)d_in[4];
    const float* enc_b    = (const float*)d_in[5];
    const float* rnn_w    = (const float*)d_in[6];
    const float* rnn_b    = (const float*)d_in[7];
    const float* act_w    = (const float*)d_in[8];
    const float* act_b    = (const float*)d_in[9];
    const float* base_w   = (const float*)d_in[10];
    const float* base_b   = (const float*)d_in[11];
    const float* comm_w   = (const float*)d_in[12];
    const float* comm_b   = (const float*)d_in[13];
    float* out = (float*)d_out;

    fused_kernel<<<NBLOCKS, 256>>>(inp, prev_hid, comm_in, ids,
                                   enc_w, enc_b, rnn_w, rnn_b,
                                   act_w, act_b, base_w, base_b,
                                   comm_w, comm_b, out);
}